// round 13
// baseline (speedup 1.0000x reference)
#include <cuda_runtime.h>

#define N_NODES 100000
#define IN_C    128
#define HC      256
#define NHEAD   4
#define CDIM    64
#define NE      1600000
#define NEG     0.2f
#define BNEPS   1e-5f

// ---- device scratch (allocation-free: __device__ globals) ----
__device__ float g_h[N_NODES * HC];          // projected features  [N,256]
__device__ float g_asrc[N_NODES * NHEAD];    // per-node src logits [N,4]
__device__ float g_adst[N_NODES * NHEAD];    // per-node dst logits [N,4]
__device__ int   g_cnt[N_NODES];             // in-degree histogram
__device__ int   g_rowptr[N_NODES + 1];      // CSR row pointers (by dst)
__device__ int   g_fill[N_NODES];            // fill cursors
__device__ int   g_csr[NE];                  // src ids grouped by dst
__device__ int   g_part[128];                // scan partials
__device__ int   g_part2[128];
__device__ float g_stat[2 * HC];             // per-channel sum / sumsq
__device__ float g_scale[HC];
__device__ float g_shift[HC];
__device__ int   g_i64;                      // 1 if edge_index is int64

// ---------------------------------------------------------------------------
__global__ void probe_kernel(const int* __restrict__ ei32) {
    int v = 0;
    for (int k = 0; k < 1024; k++) v |= ei32[2 * k + 1];
    g_i64 = (v == 0) ? 1 : 0;
}

__device__ __forceinline__ int load_edge(const void* ei, int idx) {
    if (g_i64) return (int)((const long long*)ei)[idx];
    return ((const int*)ei)[idx];
}

// ---------------------------------------------------------------------------
__global__ void init_kernel() {
    int i = blockIdx.x * blockDim.x + threadIdx.x;
    if (i < N_NODES) g_cnt[i] = 0;
    if (i < 2 * HC)  g_stat[i] = 0.f;
}

// ---------------------------------------------------------------------------
// GEMM: g_h = x @ W (100000x128 @ 128x256), 64x256 block tile, thread tile
// 16 rows x 4 cols as packed f32x2 over row pairs. Double-buffered k-pipeline:
// W tiles via cp.async (no staging regs), X tile via 4 regs; next tile's
// loads issue before current tile's compute -> LDG latency hidden.
__global__ __launch_bounds__(256) void gemm_kernel(const float* __restrict__ x,
                                                   const float* __restrict__ W,
                                                   const float* __restrict__ att_src,
                                                   const float* __restrict__ att_dst) {
    __shared__ __align__(16) float Ws[2][16][256];
    __shared__ __align__(16) float Xs[2][16][64];
    const int rowbase = blockIdx.x * 64;
    const int tid  = threadIdx.x;
    const int w    = tid >> 5;
    const int lane = tid & 31;
    const int rg   = w & 3;                 // rows rg*16 .. +16
    const int colbase = (w >> 2) * 128 + lane * 4;

    unsigned long long acc2[8][4];          // [row-pair][col]
    #pragma unroll
    for (int rp = 0; rp < 8; rp++)
        #pragma unroll
        for (int c = 0; c < 4; c++) acc2[rp][c] = 0ull;

    const int xr = tid >> 2, xq = tid & 3;  // X stage mapping
    const int xrow = rowbase + xr;

    // ---- prologue: tile 0 ----
    {
        #pragma unroll
        for (int i = 0; i < 4; i++) {
            int idx = tid + i * 256;
            int k = idx >> 6, c4 = idx & 63;
            unsigned dst = (unsigned)__cvta_generic_to_shared(&Ws[0][k][c4 * 4]);
            const float4* src = (const float4*)(W + k * 256 + c4 * 4);
            asm volatile("cp.async.ca.shared.global [%0], [%1], 16;" :: "r"(dst), "l"(src));
        }
        asm volatile("cp.async.commit_group;");
        float4 xv = make_float4(0.f, 0.f, 0.f, 0.f);
        if (xrow < N_NODES) xv = *(const float4*)(x + xrow * IN_C + xq * 4);
        Xs[0][xq * 4 + 0][xr] = xv.x; Xs[0][xq * 4 + 1][xr] = xv.y;
        Xs[0][xq * 4 + 2][xr] = xv.z; Xs[0][xq * 4 + 3][xr] = xv.w;
        asm volatile("cp.async.wait_group 0;");
    }
    __syncthreads();

    #pragma unroll
    for (int t = 0; t < 8; t++) {
        const int cur = t & 1, nxt = cur ^ 1;
        float4 xv;
        if (t < 7) {
            int k0 = (t + 1) * 16;
            #pragma unroll
            for (int i = 0; i < 4; i++) {
                int idx = tid + i * 256;
                int k = idx >> 6, c4 = idx & 63;
                unsigned dst = (unsigned)__cvta_generic_to_shared(&Ws[nxt][k][c4 * 4]);
                const float4* src = (const float4*)(W + (k0 + k) * 256 + c4 * 4);
                asm volatile("cp.async.ca.shared.global [%0], [%1], 16;" :: "r"(dst), "l"(src));
            }
            asm volatile("cp.async.commit_group;");
            xv = make_float4(0.f, 0.f, 0.f, 0.f);
            if (xrow < N_NODES) xv = *(const float4*)(x + xrow * IN_C + k0 + xq * 4);
        }

        #pragma unroll
        for (int k = 0; k < 16; k++) {
            ulonglong2 xp0 = *(const ulonglong2*)&Xs[cur][k][rg * 16];
            ulonglong2 xp1 = *(const ulonglong2*)&Xs[cur][k][rg * 16 + 4];
            ulonglong2 xp2 = *(const ulonglong2*)&Xs[cur][k][rg * 16 + 8];
            ulonglong2 xp3 = *(const ulonglong2*)&Xs[cur][k][rg * 16 + 12];
            unsigned long long xd[8] = {xp0.x, xp0.y, xp1.x, xp1.y,
                                        xp2.x, xp2.y, xp3.x, xp3.y};
            float4 wv = *(const float4*)&Ws[cur][k][colbase];
            unsigned long long wd[4];
            asm("mov.b64 %0, {%1, %1};" : "=l"(wd[0]) : "f"(wv.x));
            asm("mov.b64 %0, {%1, %1};" : "=l"(wd[1]) : "f"(wv.y));
            asm("mov.b64 %0, {%1, %1};" : "=l"(wd[2]) : "f"(wv.z));
            asm("mov.b64 %0, {%1, %1};" : "=l"(wd[3]) : "f"(wv.w));
            #pragma unroll
            for (int rp = 0; rp < 8; rp++) {
                asm("fma.rn.f32x2 %0, %1, %2, %0;" : "+l"(acc2[rp][0]) : "l"(xd[rp]), "l"(wd[0]));
                asm("fma.rn.f32x2 %0, %1, %2, %0;" : "+l"(acc2[rp][1]) : "l"(xd[rp]), "l"(wd[1]));
                asm("fma.rn.f32x2 %0, %1, %2, %0;" : "+l"(acc2[rp][2]) : "l"(xd[rp]), "l"(wd[2]));
                asm("fma.rn.f32x2 %0, %1, %2, %0;" : "+l"(acc2[rp][3]) : "l"(xd[rp]), "l"(wd[3]));
            }
        }

        if (t < 7) {
            Xs[nxt][xq * 4 + 0][xr] = xv.x; Xs[nxt][xq * 4 + 1][xr] = xv.y;
            Xs[nxt][xq * 4 + 2][xr] = xv.z; Xs[nxt][xq * 4 + 3][xr] = xv.w;
            asm volatile("cp.async.wait_group 0;");
        }
        __syncthreads();
    }

    // epilogue: store + fused a_src/a_dst (16-lane segmented reduce per head)
    const float4 atsv = *(const float4*)(att_src + colbase);
    const float4 atdv = *(const float4*)(att_dst + colbase);
    const int head = colbase >> 6;

    #pragma unroll
    for (int rp = 0; rp < 8; rp++) {
        float r0[4], r1[4];
        #pragma unroll
        for (int c = 0; c < 4; c++)
            asm("mov.b64 {%0, %1}, %2;" : "=f"(r0[c]), "=f"(r1[c]) : "l"(acc2[rp][c]));
        int row0 = rowbase + rg * 16 + 2 * rp;
        int row1 = row0 + 1;
        if (row0 < N_NODES) *(float4*)(g_h + (size_t)row0 * 256 + colbase) = *(float4*)r0;
        if (row1 < N_NODES) *(float4*)(g_h + (size_t)row1 * 256 + colbase) = *(float4*)r1;

        float as0 = r0[0]*atsv.x + r0[1]*atsv.y + r0[2]*atsv.z + r0[3]*atsv.w;
        float ad0 = r0[0]*atdv.x + r0[1]*atdv.y + r0[2]*atdv.z + r0[3]*atdv.w;
        float as1 = r1[0]*atsv.x + r1[1]*atsv.y + r1[2]*atsv.z + r1[3]*atsv.w;
        float ad1 = r1[0]*atdv.x + r1[1]*atdv.y + r1[2]*atdv.z + r1[3]*atdv.w;
        #pragma unroll
        for (int o = 8; o; o >>= 1) {
            as0 += __shfl_down_sync(0xFFFFFFFFu, as0, o, 16);
            ad0 += __shfl_down_sync(0xFFFFFFFFu, ad0, o, 16);
            as1 += __shfl_down_sync(0xFFFFFFFFu, as1, o, 16);
            ad1 += __shfl_down_sync(0xFFFFFFFFu, ad1, o, 16);
        }
        if ((lane & 15) == 0) {
            if (row0 < N_NODES) { g_asrc[row0 * 4 + head] = as0; g_adst[row0 * 4 + head] = ad0; }
            if (row1 < N_NODES) { g_asrc[row1 * 4 + head] = as1; g_adst[row1 * 4 + head] = ad1; }
        }
    }
}

// ---------------------------------------------------------------------------
__global__ void hist_kernel(const void* __restrict__ ei) {
    int i = blockIdx.x * blockDim.x + threadIdx.x;
    if (i < NE) {
        int d = load_edge(ei, NE + i);
        if ((unsigned)d < (unsigned)N_NODES) atomicAdd(&g_cnt[d], 1);
    }
}

__global__ __launch_bounds__(1024) void scan1_kernel() {
    __shared__ int sh[1024];
    int i = blockIdx.x * 1024 + threadIdx.x;
    int v = (i < N_NODES) ? g_cnt[i] : 0;
    sh[threadIdx.x] = v; __syncthreads();
    for (int off = 1; off < 1024; off <<= 1) {
        int t = (threadIdx.x >= off) ? sh[threadIdx.x - off] : 0;
        __syncthreads();
        sh[threadIdx.x] += t; __syncthreads();
    }
    if (i < N_NODES) g_rowptr[i] = sh[threadIdx.x] - v;  // exclusive
    if (threadIdx.x == 1023) g_part[blockIdx.x] = sh[1023];
}

__global__ __launch_bounds__(128) void scan2_kernel(int nb) {
    __shared__ int sh[128];
    int v = (threadIdx.x < nb) ? g_part[threadIdx.x] : 0;
    sh[threadIdx.x] = v; __syncthreads();
    for (int off = 1; off < 128; off <<= 1) {
        int t = (threadIdx.x >= off) ? sh[threadIdx.x - off] : 0;
        __syncthreads();
        sh[threadIdx.x] += t; __syncthreads();
    }
    if (threadIdx.x < nb) g_part2[threadIdx.x] = sh[threadIdx.x] - v;
    if (threadIdx.x == nb - 1) g_rowptr[N_NODES] = sh[threadIdx.x]; // total valid
}

__global__ __launch_bounds__(1024) void scan3_kernel() {
    int i = blockIdx.x * 1024 + threadIdx.x;
    if (i < N_NODES) {
        int v = g_rowptr[i] + g_part2[blockIdx.x];
        g_rowptr[i] = v;
        g_fill[i] = v;
    }
}

__global__ void fill_kernel(const void* __restrict__ ei) {
    int i = blockIdx.x * blockDim.x + threadIdx.x;
    if (i < NE) {
        int s = load_edge(ei, i);
        int d = load_edge(ei, NE + i);
        if ((unsigned)s < (unsigned)N_NODES && (unsigned)d < (unsigned)N_NODES) {
            int pos = atomicAdd(&g_fill[d], 1);
            g_csr[pos] = s;
        }
    }
}

// ---------------------------------------------------------------------------
// Aggregate: one WARP per (node, head), single pass, 8-deep load pipelining
// (16 independent 128B lines in flight per warp iteration).
__global__ __launch_bounds__(256) void agg_kernel(const float* __restrict__ bias,
                                                  float* __restrict__ out) {
    const int warp = threadIdx.x >> 5;
    const int lane = threadIdx.x & 31;
    const int node = blockIdx.x * 2 + (warp >> 2);
    const int hd   = warp & 3;
    if (node >= N_NODES) return;

    const int ebase = g_rowptr[node];
    const int deg   = g_rowptr[node + 1] - ebase;
    const float adh = g_adst[node * 4 + hd];
    const int   off = hd * 64;

    // self-loop (unnormalized)
    float e = g_asrc[node * 4 + hd] + adh;
    e = e > 0.f ? e : NEG * e;
    const float exself = __expf(e);

    const float* hi = g_h + (size_t)node * 256 + off;
    float x0 = hi[lane] * exself,      x1 = 0.f, x2 = 0.f, x3 = 0.f;
    float y0 = hi[lane + 32] * exself, y1 = 0.f, y2 = 0.f, y3 = 0.f;
    float den = 0.f;   // lane-local partial of edge exp-sum

    for (int base = 0; base < deg; base += 32) {
        const int m = min(32, deg - base);
        int   sl = 0; float al = 0.f;
        if (lane < m) {
            sl = g_csr[ebase + base + lane];
            float t = g_asrc[sl * 4 + hd] + adh;
            t = t > 0.f ? t : NEG * t;
            al = __expf(t);
        }
        den += al;
        int k = 0;
        for (; k + 8 <= m; k += 8) {
            int   s0 = __shfl_sync(0xFFFFFFFFu, sl, k);
            int   s1 = __shfl_sync(0xFFFFFFFFu, sl, k + 1);
            int   s2 = __shfl_sync(0xFFFFFFFFu, sl, k + 2);
            int   s3 = __shfl_sync(0xFFFFFFFFu, sl, k + 3);
            int   s4 = __shfl_sync(0xFFFFFFFFu, sl, k + 4);
            int   s5 = __shfl_sync(0xFFFFFFFFu, sl, k + 5);
            int   s6 = __shfl_sync(0xFFFFFFFFu, sl, k + 6);
            int   s7 = __shfl_sync(0xFFFFFFFFu, sl, k + 7);
            float w0 = __shfl_sync(0xFFFFFFFFu, al, k);
            float w1 = __shfl_sync(0xFFFFFFFFu, al, k + 1);
            float w2 = __shfl_sync(0xFFFFFFFFu, al, k + 2);
            float w3 = __shfl_sync(0xFFFFFFFFu, al, k + 3);
            float w4 = __shfl_sync(0xFFFFFFFFu, al, k + 4);
            float w5 = __shfl_sync(0xFFFFFFFFu, al, k + 5);
            float w6 = __shfl_sync(0xFFFFFFFFu, al, k + 6);
            float w7 = __shfl_sync(0xFFFFFFFFu, al, k + 7);
            const float* p0 = g_h + (size_t)s0 * 256 + off;
            const float* p1 = g_h + (size_t)s1 * 256 + off;
            const float* p2 = g_h + (size_t)s2 * 256 + off;
            const float* p3 = g_h + (size_t)s3 * 256 + off;
            const float* p4 = g_h + (size_t)s4 * 256 + off;
            const float* p5 = g_h + (size_t)s5 * 256 + off;
            const float* p6 = g_h + (size_t)s6 * 256 + off;
            const float* p7 = g_h + (size_t)s7 * 256 + off;
            x0 += p0[lane] * w0;  y0 += p0[lane + 32] * w0;
            x1 += p1[lane] * w1;  y1 += p1[lane + 32] * w1;
            x2 += p2[lane] * w2;  y2 += p2[lane + 32] * w2;
            x3 += p3[lane] * w3;  y3 += p3[lane + 32] * w3;
            x0 += p4[lane] * w4;  y0 += p4[lane + 32] * w4;
            x1 += p5[lane] * w5;  y1 += p5[lane + 32] * w5;
            x2 += p6[lane] * w6;  y2 += p6[lane + 32] * w6;
            x3 += p7[lane] * w7;  y3 += p7[lane + 32] * w7;
        }
        for (; k < m; k++) {
            int   s0 = __shfl_sync(0xFFFFFFFFu, sl, k);
            float w0 = __shfl_sync(0xFFFFFFFFu, al, k);
            const float* p0 = g_h + (size_t)s0 * 256 + off;
            x0 += p0[lane] * w0;  y0 += p0[lane + 32] * w0;
        }
    }
    #pragma unroll
    for (int o = 16; o; o >>= 1) den += __shfl_xor_sync(0xFFFFFFFFu, den, o);
    const float inv = 1.f / (den + exself + 1e-16f);

    float* po = out + (size_t)node * 256 + off;
    po[lane]      = ((x0 + x1) + (x2 + x3)) * inv + bias[off + lane];
    po[lane + 32] = ((y0 + y1) + (y2 + y3)) * inv + bias[off + lane + 32];
}

// ---------------------------------------------------------------------------
__global__ __launch_bounds__(256) void bnstat_kernel(const float* __restrict__ out) {
    int t = threadIdx.x;
    int r0 = blockIdx.x * 256;
    int rmax = min(256, N_NODES - r0);
    float s = 0.f, s2 = 0.f;
    for (int r = 0; r < rmax; r++) {
        float v = out[(size_t)(r0 + r) * 256 + t];
        s += v; s2 += v * v;
    }
    atomicAdd(&g_stat[t], s);
    atomicAdd(&g_stat[256 + t], s2);
}

__global__ __launch_bounds__(256) void bnfin_kernel(const float* __restrict__ gamma,
                                                    const float* __restrict__ beta) {
    int t = threadIdx.x;
    float invN = 1.f / (float)N_NODES;
    float mean = g_stat[t] * invN;
    float var = g_stat[256 + t] * invN - mean * mean;
    float sc = gamma[t] * rsqrtf(var + BNEPS);
    g_scale[t] = sc;
    g_shift[t] = beta[t] - mean * sc;
}

__global__ __launch_bounds__(256) void final_kernel(float* __restrict__ out) {
    int i4 = blockIdx.x * 256 + threadIdx.x;
    if (i4 >= N_NODES * (HC / 4)) return;
    int c = (i4 & 63) * 4;
    float4 v = ((float4*)out)[i4];
    float f;
    f = g_scale[c + 0] * v.x + g_shift[c + 0]; v.x = f > 0.f ? f : expm1f(f);
    f = g_scale[c + 1] * v.y + g_shift[c + 1]; v.y = f > 0.f ? f : expm1f(f);
    f = g_scale[c + 2] * v.z + g_shift[c + 2]; v.z = f > 0.f ? f : expm1f(f);
    f = g_scale[c + 3] * v.w + g_shift[c + 3]; v.w = f > 0.f ? f : expm1f(f);
    ((float4*)out)[i4] = v;
}

// ---------------------------------------------------------------------------
extern "C" void kernel_launch(void* const* d_in, const int* in_sizes, int n_in,
                              void* d_out, int out_size) {
    const float* x       = (const float*)d_in[0];
    const void*  ei      = d_in[1];
    const float* W       = (const float*)d_in[2];
    const float* att_src = (const float*)d_in[3];
    const float* att_dst = (const float*)d_in[4];
    const float* bias    = (const float*)d_in[5];
    const float* gamma   = (const float*)d_in[6];
    const float* beta    = (const float*)d_in[7];
    float* out = (float*)d_out;

    probe_kernel<<<1, 1>>>((const int*)ei);
    init_kernel<<<(N_NODES + 255) / 256, 256>>>();

    hist_kernel<<<(NE + 255) / 256, 256>>>(ei);
    gemm_kernel<<<(N_NODES + 63) / 64, 256>>>(x, W, att_src, att_dst);

    int nb = (N_NODES + 1023) / 1024;   // 98
    scan1_kernel<<<nb, 1024>>>();
    scan2_kernel<<<1, 128>>>(nb);
    scan3_kernel<<<nb, 1024>>>();
    fill_kernel<<<(NE + 255) / 256, 256>>>(ei);

    agg_kernel<<<(N_NODES + 1) / 2, 256>>>(bias, out);

    bnstat_kernel<<<(N_NODES + 255) / 256, 256>>>(out);
    bnfin_kernel<<<1, 256>>>(gamma, beta);
    final_kernel<<<(N_NODES * (HC / 4) + 255) / 256, 256>>>(out);
}

// round 15
// speedup vs baseline: 1.1614x; 1.1614x over previous
#include <cuda_runtime.h>

#define N_NODES 100000
#define IN_C    128
#define HC      256
#define NHEAD   4
#define CDIM    64
#define NE      1600000
#define NEG     0.2f
#define BNEPS   1e-5f

// ---- device scratch (allocation-free: __device__ globals) ----
__device__ float g_h[N_NODES * HC];          // projected features  [N,256]
__device__ float g_asrc[N_NODES * NHEAD];    // per-node src logits [N,4]
__device__ float g_adst[N_NODES * NHEAD];    // per-node dst logits [N,4]
__device__ int   g_cnt[N_NODES];             // in-degree histogram
__device__ int   g_rowptr[N_NODES + 1];      // CSR row pointers (by dst)
__device__ int   g_fill[N_NODES];            // fill cursors
__device__ int   g_csr[NE];                  // src ids grouped by dst
__device__ int   g_part[128];                // scan partials
__device__ int   g_part2[128];
__device__ float g_stat[2 * HC];             // per-channel sum / sumsq
__device__ float g_scale[HC];
__device__ float g_shift[HC];
__device__ int   g_i64;                      // 1 if edge_index is int64

// ---------------------------------------------------------------------------
__global__ void probe_kernel(const int* __restrict__ ei32) {
    int v = 0;
    for (int k = 0; k < 1024; k++) v |= ei32[2 * k + 1];
    g_i64 = (v == 0) ? 1 : 0;
}

__device__ __forceinline__ int load_edge(const void* ei, int idx) {
    if (g_i64) return (int)((const long long*)ei)[idx];
    return ((const int*)ei)[idx];
}

// ---------------------------------------------------------------------------
__global__ void init_kernel() {
    int i = blockIdx.x * blockDim.x + threadIdx.x;
    if (i < N_NODES) g_cnt[i] = 0;
    if (i < 2 * HC)  g_stat[i] = 0.f;
}

// ---------------------------------------------------------------------------
// GEMM: g_h = x @ W (100000x128 @ 128x256), 64x256 block tile, thread tile
// 16 rows x 4 cols as packed f32x2 over row pairs.
// Double-buffered over k-chunks of 8 (footprint 20.5KB -> 2 blocks/SM kept);
// W tiles via cp.async (zero staging regs), X via one float2/thread.
// __launch_bounds__(256,2) pins regs <= 128 so occupancy cannot collapse.
__global__ __launch_bounds__(256, 2) void gemm_kernel(const float* __restrict__ x,
                                                      const float* __restrict__ W,
                                                      const float* __restrict__ att_src,
                                                      const float* __restrict__ att_dst) {
    __shared__ __align__(16) float Ws[2][8][256];
    __shared__ __align__(16) float Xs[2][8][64];
    const int rowbase = blockIdx.x * 64;
    const int tid  = threadIdx.x;
    const int w    = tid >> 5;
    const int lane = tid & 31;
    const int rg   = w & 3;                 // rows rg*16 .. +16
    const int colbase = (w >> 2) * 128 + lane * 4;

    unsigned long long acc2[8][4];          // [row-pair][col]
    #pragma unroll
    for (int rp = 0; rp < 8; rp++)
        #pragma unroll
        for (int c = 0; c < 4; c++) acc2[rp][c] = 0ull;

    // W stage mapping: 2 float4 per thread per chunk
    const int wk0 = tid >> 6, wc0 = tid & 63;          // idx 0..255
    const int wk1 = (tid + 256) >> 6, wc1 = tid & 63;  // idx 256..511
    // X stage mapping: one float2 per thread
    const int xr = tid >> 2, xq = tid & 3;             // row 0..63, k-pair 0..3
    const int xrow = rowbase + xr;

    // ---- prologue: chunk 0 ----
    {
        unsigned d0 = (unsigned)__cvta_generic_to_shared(&Ws[0][wk0][wc0 * 4]);
        unsigned d1 = (unsigned)__cvta_generic_to_shared(&Ws[0][wk1][wc1 * 4]);
        asm volatile("cp.async.ca.shared.global [%0], [%1], 16;" :: "r"(d0), "l"(W + wk0 * 256 + wc0 * 4));
        asm volatile("cp.async.ca.shared.global [%0], [%1], 16;" :: "r"(d1), "l"(W + wk1 * 256 + wc1 * 4));
        asm volatile("cp.async.commit_group;");
        float2 xv = make_float2(0.f, 0.f);
        if (xrow < N_NODES) xv = *(const float2*)(x + xrow * IN_C + xq * 2);
        Xs[0][xq * 2 + 0][xr] = xv.x;
        Xs[0][xq * 2 + 1][xr] = xv.y;
        asm volatile("cp.async.wait_group 0;");
    }
    __syncthreads();

    for (int t = 0; t < 16; t++) {
        const int cur = t & 1, nxt = cur ^ 1;
        float2 xv;
        if (t < 15) {
            const float* wsrc = W + (t + 1) * 8 * 256;
            unsigned d0 = (unsigned)__cvta_generic_to_shared(&Ws[nxt][wk0][wc0 * 4]);
            unsigned d1 = (unsigned)__cvta_generic_to_shared(&Ws[nxt][wk1][wc1 * 4]);
            asm volatile("cp.async.ca.shared.global [%0], [%1], 16;" :: "r"(d0), "l"(wsrc + wk0 * 256 + wc0 * 4));
            asm volatile("cp.async.ca.shared.global [%0], [%1], 16;" :: "r"(d1), "l"(wsrc + wk1 * 256 + wc1 * 4));
            asm volatile("cp.async.commit_group;");
            xv = make_float2(0.f, 0.f);
            if (xrow < N_NODES) xv = *(const float2*)(x + xrow * IN_C + (t + 1) * 8 + xq * 2);
        }

        #pragma unroll
        for (int k = 0; k < 8; k++) {
            ulonglong2 xp0 = *(const ulonglong2*)&Xs[cur][k][rg * 16];
            ulonglong2 xp1 = *(const ulonglong2*)&Xs[cur][k][rg * 16 + 4];
            ulonglong2 xp2 = *(const ulonglong2*)&Xs[cur][k][rg * 16 + 8];
            ulonglong2 xp3 = *(const ulonglong2*)&Xs[cur][k][rg * 16 + 12];
            unsigned long long xd[8] = {xp0.x, xp0.y, xp1.x, xp1.y,
                                        xp2.x, xp2.y, xp3.x, xp3.y};
            float4 wv = *(const float4*)&Ws[cur][k][colbase];
            unsigned long long wd[4];
            asm("mov.b64 %0, {%1, %1};" : "=l"(wd[0]) : "f"(wv.x));
            asm("mov.b64 %0, {%1, %1};" : "=l"(wd[1]) : "f"(wv.y));
            asm("mov.b64 %0, {%1, %1};" : "=l"(wd[2]) : "f"(wv.z));
            asm("mov.b64 %0, {%1, %1};" : "=l"(wd[3]) : "f"(wv.w));
            #pragma unroll
            for (int rp = 0; rp < 8; rp++) {
                asm("fma.rn.f32x2 %0, %1, %2, %0;" : "+l"(acc2[rp][0]) : "l"(xd[rp]), "l"(wd[0]));
                asm("fma.rn.f32x2 %0, %1, %2, %0;" : "+l"(acc2[rp][1]) : "l"(xd[rp]), "l"(wd[1]));
                asm("fma.rn.f32x2 %0, %1, %2, %0;" : "+l"(acc2[rp][2]) : "l"(xd[rp]), "l"(wd[2]));
                asm("fma.rn.f32x2 %0, %1, %2, %0;" : "+l"(acc2[rp][3]) : "l"(xd[rp]), "l"(wd[3]));
            }
        }

        if (t < 15) {
            Xs[nxt][xq * 2 + 0][xr] = xv.x;
            Xs[nxt][xq * 2 + 1][xr] = xv.y;
            asm volatile("cp.async.wait_group 0;");
        }
        __syncthreads();
    }

    // epilogue: store + fused a_src/a_dst (16-lane segmented reduce per head)
    const float4 atsv = *(const float4*)(att_src + colbase);
    const float4 atdv = *(const float4*)(att_dst + colbase);
    const int head = colbase >> 6;

    #pragma unroll
    for (int rp = 0; rp < 8; rp++) {
        float r0[4], r1[4];
        #pragma unroll
        for (int c = 0; c < 4; c++)
            asm("mov.b64 {%0, %1}, %2;" : "=f"(r0[c]), "=f"(r1[c]) : "l"(acc2[rp][c]));
        int row0 = rowbase + rg * 16 + 2 * rp;
        int row1 = row0 + 1;
        if (row0 < N_NODES) *(float4*)(g_h + (size_t)row0 * 256 + colbase) = *(float4*)r0;
        if (row1 < N_NODES) *(float4*)(g_h + (size_t)row1 * 256 + colbase) = *(float4*)r1;

        float as0 = r0[0]*atsv.x + r0[1]*atsv.y + r0[2]*atsv.z + r0[3]*atsv.w;
        float ad0 = r0[0]*atdv.x + r0[1]*atdv.y + r0[2]*atdv.z + r0[3]*atdv.w;
        float as1 = r1[0]*atsv.x + r1[1]*atsv.y + r1[2]*atsv.z + r1[3]*atsv.w;
        float ad1 = r1[0]*atdv.x + r1[1]*atdv.y + r1[2]*atdv.z + r1[3]*atdv.w;
        #pragma unroll
        for (int o = 8; o; o >>= 1) {
            as0 += __shfl_down_sync(0xFFFFFFFFu, as0, o, 16);
            ad0 += __shfl_down_sync(0xFFFFFFFFu, ad0, o, 16);
            as1 += __shfl_down_sync(0xFFFFFFFFu, as1, o, 16);
            ad1 += __shfl_down_sync(0xFFFFFFFFu, ad1, o, 16);
        }
        if ((lane & 15) == 0) {
            if (row0 < N_NODES) { g_asrc[row0 * 4 + head] = as0; g_adst[row0 * 4 + head] = ad0; }
            if (row1 < N_NODES) { g_asrc[row1 * 4 + head] = as1; g_adst[row1 * 4 + head] = ad1; }
        }
    }
}

// ---------------------------------------------------------------------------
__global__ void hist_kernel(const void* __restrict__ ei) {
    int i = blockIdx.x * blockDim.x + threadIdx.x;
    if (i < NE) {
        int d = load_edge(ei, NE + i);
        if ((unsigned)d < (unsigned)N_NODES) atomicAdd(&g_cnt[d], 1);
    }
}

__global__ __launch_bounds__(1024) void scan1_kernel() {
    __shared__ int sh[1024];
    int i = blockIdx.x * 1024 + threadIdx.x;
    int v = (i < N_NODES) ? g_cnt[i] : 0;
    sh[threadIdx.x] = v; __syncthreads();
    for (int off = 1; off < 1024; off <<= 1) {
        int t = (threadIdx.x >= off) ? sh[threadIdx.x - off] : 0;
        __syncthreads();
        sh[threadIdx.x] += t; __syncthreads();
    }
    if (i < N_NODES) g_rowptr[i] = sh[threadIdx.x] - v;  // exclusive
    if (threadIdx.x == 1023) g_part[blockIdx.x] = sh[1023];
}

__global__ __launch_bounds__(128) void scan2_kernel(int nb) {
    __shared__ int sh[128];
    int v = (threadIdx.x < nb) ? g_part[threadIdx.x] : 0;
    sh[threadIdx.x] = v; __syncthreads();
    for (int off = 1; off < 128; off <<= 1) {
        int t = (threadIdx.x >= off) ? sh[threadIdx.x - off] : 0;
        __syncthreads();
        sh[threadIdx.x] += t; __syncthreads();
    }
    if (threadIdx.x < nb) g_part2[threadIdx.x] = sh[threadIdx.x] - v;
    if (threadIdx.x == nb - 1) g_rowptr[N_NODES] = sh[threadIdx.x]; // total valid
}

__global__ __launch_bounds__(1024) void scan3_kernel() {
    int i = blockIdx.x * 1024 + threadIdx.x;
    if (i < N_NODES) {
        int v = g_rowptr[i] + g_part2[blockIdx.x];
        g_rowptr[i] = v;
        g_fill[i] = v;
    }
}

__global__ void fill_kernel(const void* __restrict__ ei) {
    int i = blockIdx.x * blockDim.x + threadIdx.x;
    if (i < NE) {
        int s = load_edge(ei, i);
        int d = load_edge(ei, NE + i);
        if ((unsigned)s < (unsigned)N_NODES && (unsigned)d < (unsigned)N_NODES) {
            int pos = atomicAdd(&g_fill[d], 1);
            g_csr[pos] = s;
        }
    }
}

// ---------------------------------------------------------------------------
// Aggregate: one WARP per (node, head), single pass (R12-proven version).
__global__ __launch_bounds__(256) void agg_kernel(const float* __restrict__ bias,
                                                  float* __restrict__ out) {
    const int warp = threadIdx.x >> 5;
    const int lane = threadIdx.x & 31;
    const int node = blockIdx.x * 2 + (warp >> 2);
    const int hd   = warp & 3;
    if (node >= N_NODES) return;

    const int ebase = g_rowptr[node];
    const int deg   = g_rowptr[node + 1] - ebase;
    const float adh = g_adst[node * 4 + hd];
    const int   off = hd * 64;

    // self-loop (unnormalized)
    float e = g_asrc[node * 4 + hd] + adh;
    e = e > 0.f ? e : NEG * e;
    const float exself = __expf(e);

    const float* hi = g_h + (size_t)node * 256 + off;
    float x0 = hi[lane] * exself,      x1 = 0.f;
    float y0 = hi[lane + 32] * exself, y1 = 0.f;
    float den = 0.f;   // lane-local partial of edge exp-sum

    for (int base = 0; base < deg; base += 32) {
        const int m = min(32, deg - base);
        int   sl = 0; float al = 0.f;
        if (lane < m) {
            sl = g_csr[ebase + base + lane];
            float t = g_asrc[sl * 4 + hd] + adh;
            t = t > 0.f ? t : NEG * t;
            al = __expf(t);
        }
        den += al;
        int k = 0;
        for (; k + 4 <= m; k += 4) {
            int   s0 = __shfl_sync(0xFFFFFFFFu, sl, k);
            int   s1 = __shfl_sync(0xFFFFFFFFu, sl, k + 1);
            int   s2 = __shfl_sync(0xFFFFFFFFu, sl, k + 2);
            int   s3 = __shfl_sync(0xFFFFFFFFu, sl, k + 3);
            float w0 = __shfl_sync(0xFFFFFFFFu, al, k);
            float w1 = __shfl_sync(0xFFFFFFFFu, al, k + 1);
            float w2 = __shfl_sync(0xFFFFFFFFu, al, k + 2);
            float w3 = __shfl_sync(0xFFFFFFFFu, al, k + 3);
            const float* p0 = g_h + (size_t)s0 * 256 + off;
            const float* p1 = g_h + (size_t)s1 * 256 + off;
            const float* p2 = g_h + (size_t)s2 * 256 + off;
            const float* p3 = g_h + (size_t)s3 * 256 + off;
            x0 += p0[lane] * w0;  y0 += p0[lane + 32] * w0;
            x1 += p1[lane] * w1;  y1 += p1[lane + 32] * w1;
            x0 += p2[lane] * w2;  y0 += p2[lane + 32] * w2;
            x1 += p3[lane] * w3;  y1 += p3[lane + 32] * w3;
        }
        for (; k < m; k++) {
            int   s0 = __shfl_sync(0xFFFFFFFFu, sl, k);
            float w0 = __shfl_sync(0xFFFFFFFFu, al, k);
            const float* p0 = g_h + (size_t)s0 * 256 + off;
            x0 += p0[lane] * w0;  y0 += p0[lane + 32] * w0;
        }
    }
    #pragma unroll
    for (int o = 16; o; o >>= 1) den += __shfl_xor_sync(0xFFFFFFFFu, den, o);
    const float inv = 1.f / (den + exself + 1e-16f);

    float* po = out + (size_t)node * 256 + off;
    po[lane]      = (x0 + x1) * inv + bias[off + lane];
    po[lane + 32] = (y0 + y1) * inv + bias[off + lane + 32];
}

// ---------------------------------------------------------------------------
__global__ __launch_bounds__(256) void bnstat_kernel(const float* __restrict__ out) {
    int t = threadIdx.x;
    int r0 = blockIdx.x * 256;
    int rmax = min(256, N_NODES - r0);
    float s = 0.f, s2 = 0.f;
    for (int r = 0; r < rmax; r++) {
        float v = out[(size_t)(r0 + r) * 256 + t];
        s += v; s2 += v * v;
    }
    atomicAdd(&g_stat[t], s);
    atomicAdd(&g_stat[256 + t], s2);
}

__global__ __launch_bounds__(256) void bnfin_kernel(const float* __restrict__ gamma,
                                                    const float* __restrict__ beta) {
    int t = threadIdx.x;
    float invN = 1.f / (float)N_NODES;
    float mean = g_stat[t] * invN;
    float var = g_stat[256 + t] * invN - mean * mean;
    float sc = gamma[t] * rsqrtf(var + BNEPS);
    g_scale[t] = sc;
    g_shift[t] = beta[t] - mean * sc;
}

__global__ __launch_bounds__(256) void final_kernel(float* __restrict__ out) {
    int i4 = blockIdx.x * 256 + threadIdx.x;
    if (i4 >= N_NODES * (HC / 4)) return;
    int c = (i4 & 63) * 4;
    float4 v = ((float4*)out)[i4];
    float f;
    f = g_scale[c + 0] * v.x + g_shift[c + 0]; v.x = f > 0.f ? f : expm1f(f);
    f = g_scale[c + 1] * v.y + g_shift[c + 1]; v.y = f > 0.f ? f : expm1f(f);
    f = g_scale[c + 2] * v.z + g_shift[c + 2]; v.z = f > 0.f ? f : expm1f(f);
    f = g_scale[c + 3] * v.w + g_shift[c + 3]; v.w = f > 0.f ? f : expm1f(f);
    ((float4*)out)[i4] = v;
}

// ---------------------------------------------------------------------------
extern "C" void kernel_launch(void* const* d_in, const int* in_sizes, int n_in,
                              void* d_out, int out_size) {
    const float* x       = (const float*)d_in[0];
    const void*  ei      = d_in[1];
    const float* W       = (const float*)d_in[2];
    const float* att_src = (const float*)d_in[3];
    const float* att_dst = (const float*)d_in[4];
    const float* bias    = (const float*)d_in[5];
    const float* gamma   = (const float*)d_in[6];
    const float* beta    = (const float*)d_in[7];
    float* out = (float*)d_out;

    probe_kernel<<<1, 1>>>((const int*)ei);
    init_kernel<<<(N_NODES + 255) / 256, 256>>>();

    hist_kernel<<<(NE + 255) / 256, 256>>>(ei);
    gemm_kernel<<<(N_NODES + 63) / 64, 256>>>(x, W, att_src, att_dst);

    int nb = (N_NODES + 1023) / 1024;   // 98
    scan1_kernel<<<nb, 1024>>>();
    scan2_kernel<<<1, 128>>>(nb);
    scan3_kernel<<<nb, 1024>>>();
    fill_kernel<<<(NE + 255) / 256, 256>>>(ei);

    agg_kernel<<<(N_NODES + 1) / 2, 256>>>(bias, out);

    bnstat_kernel<<<(N_NODES + 255) / 256, 256>>>(out);
    bnfin_kernel<<<1, 256>>>(gamma, beta);
    final_kernel<<<(N_NODES * (HC / 4) + 255) / 256, 256>>>(out);
}

// round 16
// speedup vs baseline: 1.3237x; 1.1398x over previous
#include <cuda_runtime.h>
#include <cuda_fp16.h>

#define N_NODES 100000
#define IN_C    128
#define HC      256
#define NHEAD   4
#define CDIM    64
#define NE      1600000
#define NEG     0.2f
#define BNEPS   1e-5f

// ---- device scratch (allocation-free: __device__ globals) ----
__device__ float  g_h[N_NODES * HC];         // projected features  [N,256] fp32
__device__ __half g_h16[N_NODES * HC];       // fp16 mirror for edge gathers
__device__ float  g_asrc[N_NODES * NHEAD];   // per-node src logits [N,4]
__device__ float  g_adst[N_NODES * NHEAD];   // per-node dst logits [N,4]
__device__ int    g_cnt[N_NODES];            // in-degree histogram
__device__ int    g_rowptr[N_NODES + 1];     // CSR row pointers (by dst)
__device__ int    g_fill[N_NODES];           // fill cursors
__device__ int    g_csr[NE];                 // src ids grouped by dst
__device__ int    g_part[128];               // scan partials
__device__ int    g_part2[128];
__device__ float  g_stat[2 * HC];            // per-channel sum / sumsq
__device__ float  g_scale[HC];
__device__ float  g_shift[HC];
__device__ int    g_i64;                     // 1 if edge_index is int64

// ---------------------------------------------------------------------------
__global__ void probe_kernel(const int* __restrict__ ei32) {
    int v = 0;
    for (int k = 0; k < 1024; k++) v |= ei32[2 * k + 1];
    g_i64 = (v == 0) ? 1 : 0;
}

__device__ __forceinline__ int load_edge(const void* ei, int idx) {
    if (g_i64) return (int)((const long long*)ei)[idx];
    return ((const int*)ei)[idx];
}

// ---------------------------------------------------------------------------
__global__ void init_kernel() {
    int i = blockIdx.x * blockDim.x + threadIdx.x;
    if (i < N_NODES) g_cnt[i] = 0;
    if (i < 2 * HC)  g_stat[i] = 0.f;
}

// ---------------------------------------------------------------------------
// GEMM: g_h = x @ W (100000x128 @ 128x256), 64x256 block tile, thread tile
// 16 rows x 4 cols as packed f32x2 over row pairs (R12-proven mainloop).
// Epilogue: fp32 + fp16 stores and fused a_src/a_dst.
__global__ __launch_bounds__(256) void gemm_kernel(const float* __restrict__ x,
                                                   const float* __restrict__ W,
                                                   const float* __restrict__ att_src,
                                                   const float* __restrict__ att_dst) {
    __shared__ float Ws[16][256];
    __shared__ float Xs[16][64];
    const int rowbase = blockIdx.x * 64;
    const int tid  = threadIdx.x;
    const int w    = tid >> 5;
    const int lane = tid & 31;
    const int rg   = w & 3;                 // rows rg*16 .. +16
    const int colbase = (w >> 2) * 128 + lane * 4;

    unsigned long long acc2[8][4];          // [row-pair][col]
    #pragma unroll
    for (int rp = 0; rp < 8; rp++)
        #pragma unroll
        for (int c = 0; c < 4; c++) acc2[rp][c] = 0ull;

    for (int k0 = 0; k0 < IN_C; k0 += 16) {
        #pragma unroll
        for (int i = 0; i < 4; i++) {
            int idx = tid + i * 256;
            int k = idx >> 6, c4 = idx & 63;
            float4 wv = *(const float4*)(W + (k0 + k) * 256 + c4 * 4);
            *(float4*)(&Ws[k][c4 * 4]) = wv;
        }
        {
            int r = tid >> 2, kq = tid & 3;
            int row = rowbase + r;
            float4 xv = make_float4(0.f, 0.f, 0.f, 0.f);
            if (row < N_NODES)
                xv = *(const float4*)(x + row * IN_C + k0 + kq * 4);
            Xs[kq * 4 + 0][r] = xv.x; Xs[kq * 4 + 1][r] = xv.y;
            Xs[kq * 4 + 2][r] = xv.z; Xs[kq * 4 + 3][r] = xv.w;
        }
        __syncthreads();
        #pragma unroll
        for (int k = 0; k < 16; k++) {
            ulonglong2 xp0 = *(const ulonglong2*)&Xs[k][rg * 16];
            ulonglong2 xp1 = *(const ulonglong2*)&Xs[k][rg * 16 + 4];
            ulonglong2 xp2 = *(const ulonglong2*)&Xs[k][rg * 16 + 8];
            ulonglong2 xp3 = *(const ulonglong2*)&Xs[k][rg * 16 + 12];
            unsigned long long xd[8] = {xp0.x, xp0.y, xp1.x, xp1.y,
                                        xp2.x, xp2.y, xp3.x, xp3.y};
            float4 wv = *(const float4*)&Ws[k][colbase];
            unsigned long long wd[4];
            asm("mov.b64 %0, {%1, %1};" : "=l"(wd[0]) : "f"(wv.x));
            asm("mov.b64 %0, {%1, %1};" : "=l"(wd[1]) : "f"(wv.y));
            asm("mov.b64 %0, {%1, %1};" : "=l"(wd[2]) : "f"(wv.z));
            asm("mov.b64 %0, {%1, %1};" : "=l"(wd[3]) : "f"(wv.w));
            #pragma unroll
            for (int rp = 0; rp < 8; rp++) {
                asm("fma.rn.f32x2 %0, %1, %2, %0;" : "+l"(acc2[rp][0]) : "l"(xd[rp]), "l"(wd[0]));
                asm("fma.rn.f32x2 %0, %1, %2, %0;" : "+l"(acc2[rp][1]) : "l"(xd[rp]), "l"(wd[1]));
                asm("fma.rn.f32x2 %0, %1, %2, %0;" : "+l"(acc2[rp][2]) : "l"(xd[rp]), "l"(wd[2]));
                asm("fma.rn.f32x2 %0, %1, %2, %0;" : "+l"(acc2[rp][3]) : "l"(xd[rp]), "l"(wd[3]));
            }
        }
        __syncthreads();
    }

    // epilogue: fp32 + fp16 stores, fused a_src/a_dst (16-lane segmented reduce)
    const float4 atsv = *(const float4*)(att_src + colbase);
    const float4 atdv = *(const float4*)(att_dst + colbase);
    const int head = colbase >> 6;

    #pragma unroll
    for (int rp = 0; rp < 8; rp++) {
        float r0[4], r1[4];
        #pragma unroll
        for (int c = 0; c < 4; c++)
            asm("mov.b64 {%0, %1}, %2;" : "=f"(r0[c]), "=f"(r1[c]) : "l"(acc2[rp][c]));
        int row0 = rowbase + rg * 16 + 2 * rp;
        int row1 = row0 + 1;
        if (row0 < N_NODES) {
            *(float4*)(g_h + (size_t)row0 * 256 + colbase) = *(float4*)r0;
            union { __half2 h[2]; uint2 u; } pk;
            pk.h[0] = __floats2half2_rn(r0[0], r0[1]);
            pk.h[1] = __floats2half2_rn(r0[2], r0[3]);
            *(uint2*)(g_h16 + (size_t)row0 * 256 + colbase) = pk.u;
        }
        if (row1 < N_NODES) {
            *(float4*)(g_h + (size_t)row1 * 256 + colbase) = *(float4*)r1;
            union { __half2 h[2]; uint2 u; } pk;
            pk.h[0] = __floats2half2_rn(r1[0], r1[1]);
            pk.h[1] = __floats2half2_rn(r1[2], r1[3]);
            *(uint2*)(g_h16 + (size_t)row1 * 256 + colbase) = pk.u;
        }

        float as0 = r0[0]*atsv.x + r0[1]*atsv.y + r0[2]*atsv.z + r0[3]*atsv.w;
        float ad0 = r0[0]*atdv.x + r0[1]*atdv.y + r0[2]*atdv.z + r0[3]*atdv.w;
        float as1 = r1[0]*atsv.x + r1[1]*atsv.y + r1[2]*atsv.z + r1[3]*atsv.w;
        float ad1 = r1[0]*atdv.x + r1[1]*atdv.y + r1[2]*atdv.z + r1[3]*atdv.w;
        #pragma unroll
        for (int o = 8; o; o >>= 1) {
            as0 += __shfl_down_sync(0xFFFFFFFFu, as0, o, 16);
            ad0 += __shfl_down_sync(0xFFFFFFFFu, ad0, o, 16);
            as1 += __shfl_down_sync(0xFFFFFFFFu, as1, o, 16);
            ad1 += __shfl_down_sync(0xFFFFFFFFu, ad1, o, 16);
        }
        if ((lane & 15) == 0) {
            if (row0 < N_NODES) { g_asrc[row0 * 4 + head] = as0; g_adst[row0 * 4 + head] = ad0; }
            if (row1 < N_NODES) { g_asrc[row1 * 4 + head] = as1; g_adst[row1 * 4 + head] = ad1; }
        }
    }
}

// ---------------------------------------------------------------------------
__global__ void hist_kernel(const void* __restrict__ ei) {
    int i = blockIdx.x * blockDim.x + threadIdx.x;
    if (i < NE) {
        int d = load_edge(ei, NE + i);
        if ((unsigned)d < (unsigned)N_NODES) atomicAdd(&g_cnt[d], 1);
    }
}

__global__ __launch_bounds__(1024) void scan1_kernel() {
    __shared__ int sh[1024];
    int i = blockIdx.x * 1024 + threadIdx.x;
    int v = (i < N_NODES) ? g_cnt[i] : 0;
    sh[threadIdx.x] = v; __syncthreads();
    for (int off = 1; off < 1024; off <<= 1) {
        int t = (threadIdx.x >= off) ? sh[threadIdx.x - off] : 0;
        __syncthreads();
        sh[threadIdx.x] += t; __syncthreads();
    }
    if (i < N_NODES) g_rowptr[i] = sh[threadIdx.x] - v;  // exclusive
    if (threadIdx.x == 1023) g_part[blockIdx.x] = sh[1023];
}

__global__ __launch_bounds__(128) void scan2_kernel(int nb) {
    __shared__ int sh[128];
    int v = (threadIdx.x < nb) ? g_part[threadIdx.x] : 0;
    sh[threadIdx.x] = v; __syncthreads();
    for (int off = 1; off < 128; off <<= 1) {
        int t = (threadIdx.x >= off) ? sh[threadIdx.x - off] : 0;
        __syncthreads();
        sh[threadIdx.x] += t; __syncthreads();
    }
    if (threadIdx.x < nb) g_part2[threadIdx.x] = sh[threadIdx.x] - v;
    if (threadIdx.x == nb - 1) g_rowptr[N_NODES] = sh[threadIdx.x]; // total valid
}

__global__ __launch_bounds__(1024) void scan3_kernel() {
    int i = blockIdx.x * 1024 + threadIdx.x;
    if (i < N_NODES) {
        int v = g_rowptr[i] + g_part2[blockIdx.x];
        g_rowptr[i] = v;
        g_fill[i] = v;
    }
}

__global__ void fill_kernel(const void* __restrict__ ei) {
    int i = blockIdx.x * blockDim.x + threadIdx.x;
    if (i < NE) {
        int s = load_edge(ei, i);
        int d = load_edge(ei, NE + i);
        if ((unsigned)s < (unsigned)N_NODES && (unsigned)d < (unsigned)N_NODES) {
            int pos = atomicAdd(&g_fill[d], 1);
            g_csr[pos] = s;
        }
    }
}

// ---------------------------------------------------------------------------
// Aggregate: one WARP per (node, head), single pass. Edge gathers read the
// fp16 mirror (one 128B line per edge per warp, half the fp32 traffic); lane
// owns channel pair (2*lane, 2*lane+1). Weights/sums/output all fp32.
__global__ __launch_bounds__(256) void agg_kernel(const float* __restrict__ bias,
                                                  float* __restrict__ out) {
    const int warp = threadIdx.x >> 5;
    const int lane = threadIdx.x & 31;
    const int node = blockIdx.x * 2 + (warp >> 2);
    const int hd   = warp & 3;
    if (node >= N_NODES) return;

    const int ebase = g_rowptr[node];
    const int deg   = g_rowptr[node + 1] - ebase;
    const float adh = g_adst[node * 4 + hd];
    const int   off = hd * 64;

    // self-loop (unnormalized, fp32 row)
    float e = g_asrc[node * 4 + hd] + adh;
    e = e > 0.f ? e : NEG * e;
    const float exself = __expf(e);

    const float2 hv = ((const float2*)(g_h + (size_t)node * 256 + off))[lane];
    float ax0 = hv.x * exself, ay0 = hv.y * exself;
    float ax1 = 0.f, ay1 = 0.f;
    float den = 0.f;   // lane-local partial of edge exp-sum

    for (int base = 0; base < deg; base += 32) {
        const int m = min(32, deg - base);
        int   sl = 0; float al = 0.f;
        if (lane < m) {
            sl = g_csr[ebase + base + lane];
            float t = g_asrc[sl * 4 + hd] + adh;
            t = t > 0.f ? t : NEG * t;
            al = __expf(t);
        }
        den += al;
        int k = 0;
        for (; k + 4 <= m; k += 4) {
            int   s0 = __shfl_sync(0xFFFFFFFFu, sl, k);
            int   s1 = __shfl_sync(0xFFFFFFFFu, sl, k + 1);
            int   s2 = __shfl_sync(0xFFFFFFFFu, sl, k + 2);
            int   s3 = __shfl_sync(0xFFFFFFFFu, sl, k + 3);
            float w0 = __shfl_sync(0xFFFFFFFFu, al, k);
            float w1 = __shfl_sync(0xFFFFFFFFu, al, k + 1);
            float w2 = __shfl_sync(0xFFFFFFFFu, al, k + 2);
            float w3 = __shfl_sync(0xFFFFFFFFu, al, k + 3);
            __half2 v0 = ((const __half2*)(g_h16 + (size_t)s0 * 256 + off))[lane];
            __half2 v1 = ((const __half2*)(g_h16 + (size_t)s1 * 256 + off))[lane];
            __half2 v2 = ((const __half2*)(g_h16 + (size_t)s2 * 256 + off))[lane];
            __half2 v3 = ((const __half2*)(g_h16 + (size_t)s3 * 256 + off))[lane];
            float2 f0 = __half22float2(v0);
            float2 f1 = __half22float2(v1);
            float2 f2 = __half22float2(v2);
            float2 f3 = __half22float2(v3);
            ax0 += f0.x * w0;  ay0 += f0.y * w0;
            ax1 += f1.x * w1;  ay1 += f1.y * w1;
            ax0 += f2.x * w2;  ay0 += f2.y * w2;
            ax1 += f3.x * w3;  ay1 += f3.y * w3;
        }
        for (; k < m; k++) {
            int   s0 = __shfl_sync(0xFFFFFFFFu, sl, k);
            float w0 = __shfl_sync(0xFFFFFFFFu, al, k);
            __half2 v0 = ((const __half2*)(g_h16 + (size_t)s0 * 256 + off))[lane];
            float2 f0 = __half22float2(v0);
            ax0 += f0.x * w0;  ay0 += f0.y * w0;
        }
    }
    #pragma unroll
    for (int o = 16; o; o >>= 1) den += __shfl_xor_sync(0xFFFFFFFFu, den, o);
    const float inv = 1.f / (den + exself + 1e-16f);

    const float2 bv = ((const float2*)(bias + off))[lane];
    float2 res;
    res.x = (ax0 + ax1) * inv + bv.x;
    res.y = (ay0 + ay1) * inv + bv.y;
    ((float2*)(out + (size_t)node * 256 + off))[lane] = res;
}

// ---------------------------------------------------------------------------
__global__ __launch_bounds__(256) void bnstat_kernel(const float* __restrict__ out) {
    int t = threadIdx.x;
    int r0 = blockIdx.x * 256;
    int rmax = min(256, N_NODES - r0);
    float s = 0.f, s2 = 0.f;
    for (int r = 0; r < rmax; r++) {
        float v = out[(size_t)(r0 + r) * 256 + t];
        s += v; s2 += v * v;
    }
    atomicAdd(&g_stat[t], s);
    atomicAdd(&g_stat[256 + t], s2);
}

__global__ __launch_bounds__(256) void bnfin_kernel(const float* __restrict__ gamma,
                                                    const float* __restrict__ beta) {
    int t = threadIdx.x;
    float invN = 1.f / (float)N_NODES;
    float mean = g_stat[t] * invN;
    float var = g_stat[256 + t] * invN - mean * mean;
    float sc = gamma[t] * rsqrtf(var + BNEPS);
    g_scale[t] = sc;
    g_shift[t] = beta[t] - mean * sc;
}

__global__ __launch_bounds__(256) void final_kernel(float* __restrict__ out) {
    int i4 = blockIdx.x * 256 + threadIdx.x;
    if (i4 >= N_NODES * (HC / 4)) return;
    int c = (i4 & 63) * 4;
    float4 v = ((float4*)out)[i4];
    float f;
    f = g_scale[c + 0] * v.x + g_shift[c + 0]; v.x = f > 0.f ? f : expm1f(f);
    f = g_scale[c + 1] * v.y + g_shift[c + 1]; v.y = f > 0.f ? f : expm1f(f);
    f = g_scale[c + 2] * v.z + g_shift[c + 2]; v.z = f > 0.f ? f : expm1f(f);
    f = g_scale[c + 3] * v.w + g_shift[c + 3]; v.w = f > 0.f ? f : expm1f(f);
    ((float4*)out)[i4] = v;
}

// ---------------------------------------------------------------------------
extern "C" void kernel_launch(void* const* d_in, const int* in_sizes, int n_in,
                              void* d_out, int out_size) {
    const float* x       = (const float*)d_in[0];
    const void*  ei      = d_in[1];
    const float* W       = (const float*)d_in[2];
    const float* att_src = (const float*)d_in[3];
    const float* att_dst = (const float*)d_in[4];
    const float* bias    = (const float*)d_in[5];
    const float* gamma   = (const float*)d_in[6];
    const float* beta    = (const float*)d_in[7];
    float* out = (float*)d_out;

    probe_kernel<<<1, 1>>>((const int*)ei);
    init_kernel<<<(N_NODES + 255) / 256, 256>>>();

    hist_kernel<<<(NE + 255) / 256, 256>>>(ei);
    gemm_kernel<<<(N_NODES + 63) / 64, 256>>>(x, W, att_src, att_dst);

    int nb = (N_NODES + 1023) / 1024;   // 98
    scan1_kernel<<<nb, 1024>>>();
    scan2_kernel<<<1, 128>>>(nb);
    scan3_kernel<<<nb, 1024>>>();
    fill_kernel<<<(NE + 255) / 256, 256>>>(ei);

    agg_kernel<<<(N_NODES + 1) / 2, 256>>>(bias, out);

    bnstat_kernel<<<(N_NODES + 255) / 256, 256>>>(out);
    bnfin_kernel<<<1, 256>>>(gamma, beta);
    final_kernel<<<(N_NODES * (HC / 4) + 255) / 256, 256>>>(out);
}

// round 17
// speedup vs baseline: 1.4936x; 1.1284x over previous
#include <cuda_runtime.h>
#include <cuda_fp16.h>

#define N_NODES 100000
#define IN_C    128
#define HC      256
#define NHEAD   4
#define CDIM    64
#define NE      1600000
#define NEG     0.2f
#define BNEPS   1e-5f

// ---- device scratch (allocation-free: __device__ globals) ----
__device__ __half g_h16[N_NODES * HC];       // projected features, fp16
__device__ float  g_asrc[N_NODES * NHEAD];   // per-node src logits [N,4]
__device__ float  g_adst[N_NODES * NHEAD];   // per-node dst logits [N,4]
__device__ int    g_cnt[N_NODES];            // in-degree histogram
__device__ int    g_rowptr[N_NODES + 1];     // CSR row pointers (by dst)
__device__ int    g_fill[N_NODES];           // fill cursors
__device__ int    g_csr[NE];                 // src ids grouped by dst
__device__ int    g_part[128];               // scan partials
__device__ int    g_part2[128];
__device__ float  g_stat[2 * HC];            // per-channel sum / sumsq
__device__ float  g_scale[HC];
__device__ float  g_shift[HC];
__device__ int    g_i64;                     // 1 if edge_index is int64

// ---------------------------------------------------------------------------
__global__ void probe_kernel(const int* __restrict__ ei32) {
    int v = 0;
    for (int k = 0; k < 1024; k++) v |= ei32[2 * k + 1];
    g_i64 = (v == 0) ? 1 : 0;
}

__device__ __forceinline__ int load_edge(const void* ei, int idx) {
    if (g_i64) return (int)((const long long*)ei)[idx];
    return ((const int*)ei)[idx];
}

// ---------------------------------------------------------------------------
__global__ void init_kernel() {
    int i = blockIdx.x * blockDim.x + threadIdx.x;
    if (i < N_NODES) g_cnt[i] = 0;
    if (i < 2 * HC)  g_stat[i] = 0.f;
}

// ---------------------------------------------------------------------------
// GEMM: h = x @ W (100000x128 @ 128x256), 64x256 block tile, thread tile
// 16 rows x 4 cols as packed f32x2 over row pairs (R12-proven mainloop).
// Epilogue: fp16-only h store + fused a_src/a_dst (fp32).
__global__ __launch_bounds__(256) void gemm_kernel(const float* __restrict__ x,
                                                   const float* __restrict__ W,
                                                   const float* __restrict__ att_src,
                                                   const float* __restrict__ att_dst) {
    __shared__ float Ws[16][256];
    __shared__ float Xs[16][64];
    const int rowbase = blockIdx.x * 64;
    const int tid  = threadIdx.x;
    const int w    = tid >> 5;
    const int lane = tid & 31;
    const int rg   = w & 3;                 // rows rg*16 .. +16
    const int colbase = (w >> 2) * 128 + lane * 4;

    unsigned long long acc2[8][4];          // [row-pair][col]
    #pragma unroll
    for (int rp = 0; rp < 8; rp++)
        #pragma unroll
        for (int c = 0; c < 4; c++) acc2[rp][c] = 0ull;

    for (int k0 = 0; k0 < IN_C; k0 += 16) {
        #pragma unroll
        for (int i = 0; i < 4; i++) {
            int idx = tid + i * 256;
            int k = idx >> 6, c4 = idx & 63;
            float4 wv = *(const float4*)(W + (k0 + k) * 256 + c4 * 4);
            *(float4*)(&Ws[k][c4 * 4]) = wv;
        }
        {
            int r = tid >> 2, kq = tid & 3;
            int row = rowbase + r;
            float4 xv = make_float4(0.f, 0.f, 0.f, 0.f);
            if (row < N_NODES)
                xv = *(const float4*)(x + row * IN_C + k0 + kq * 4);
            Xs[kq * 4 + 0][r] = xv.x; Xs[kq * 4 + 1][r] = xv.y;
            Xs[kq * 4 + 2][r] = xv.z; Xs[kq * 4 + 3][r] = xv.w;
        }
        __syncthreads();
        #pragma unroll
        for (int k = 0; k < 16; k++) {
            ulonglong2 xp0 = *(const ulonglong2*)&Xs[k][rg * 16];
            ulonglong2 xp1 = *(const ulonglong2*)&Xs[k][rg * 16 + 4];
            ulonglong2 xp2 = *(const ulonglong2*)&Xs[k][rg * 16 + 8];
            ulonglong2 xp3 = *(const ulonglong2*)&Xs[k][rg * 16 + 12];
            unsigned long long xd[8] = {xp0.x, xp0.y, xp1.x, xp1.y,
                                        xp2.x, xp2.y, xp3.x, xp3.y};
            float4 wv = *(const float4*)&Ws[k][colbase];
            unsigned long long wd[4];
            asm("mov.b64 %0, {%1, %1};" : "=l"(wd[0]) : "f"(wv.x));
            asm("mov.b64 %0, {%1, %1};" : "=l"(wd[1]) : "f"(wv.y));
            asm("mov.b64 %0, {%1, %1};" : "=l"(wd[2]) : "f"(wv.z));
            asm("mov.b64 %0, {%1, %1};" : "=l"(wd[3]) : "f"(wv.w));
            #pragma unroll
            for (int rp = 0; rp < 8; rp++) {
                asm("fma.rn.f32x2 %0, %1, %2, %0;" : "+l"(acc2[rp][0]) : "l"(xd[rp]), "l"(wd[0]));
                asm("fma.rn.f32x2 %0, %1, %2, %0;" : "+l"(acc2[rp][1]) : "l"(xd[rp]), "l"(wd[1]));
                asm("fma.rn.f32x2 %0, %1, %2, %0;" : "+l"(acc2[rp][2]) : "l"(xd[rp]), "l"(wd[2]));
                asm("fma.rn.f32x2 %0, %1, %2, %0;" : "+l"(acc2[rp][3]) : "l"(xd[rp]), "l"(wd[3]));
            }
        }
        __syncthreads();
    }

    // epilogue: fp16 store + fused a_src/a_dst (16-lane segmented reduce)
    const float4 atsv = *(const float4*)(att_src + colbase);
    const float4 atdv = *(const float4*)(att_dst + colbase);
    const int head = colbase >> 6;

    #pragma unroll
    for (int rp = 0; rp < 8; rp++) {
        float r0[4], r1[4];
        #pragma unroll
        for (int c = 0; c < 4; c++)
            asm("mov.b64 {%0, %1}, %2;" : "=f"(r0[c]), "=f"(r1[c]) : "l"(acc2[rp][c]));
        int row0 = rowbase + rg * 16 + 2 * rp;
        int row1 = row0 + 1;
        if (row0 < N_NODES) {
            union { __half2 h[2]; uint2 u; } pk;
            pk.h[0] = __floats2half2_rn(r0[0], r0[1]);
            pk.h[1] = __floats2half2_rn(r0[2], r0[3]);
            *(uint2*)(g_h16 + (size_t)row0 * 256 + colbase) = pk.u;
        }
        if (row1 < N_NODES) {
            union { __half2 h[2]; uint2 u; } pk;
            pk.h[0] = __floats2half2_rn(r1[0], r1[1]);
            pk.h[1] = __floats2half2_rn(r1[2], r1[3]);
            *(uint2*)(g_h16 + (size_t)row1 * 256 + colbase) = pk.u;
        }

        float as0 = r0[0]*atsv.x + r0[1]*atsv.y + r0[2]*atsv.z + r0[3]*atsv.w;
        float ad0 = r0[0]*atdv.x + r0[1]*atdv.y + r0[2]*atdv.z + r0[3]*atdv.w;
        float as1 = r1[0]*atsv.x + r1[1]*atsv.y + r1[2]*atsv.z + r1[3]*atsv.w;
        float ad1 = r1[0]*atdv.x + r1[1]*atdv.y + r1[2]*atdv.z + r1[3]*atdv.w;
        #pragma unroll
        for (int o = 8; o; o >>= 1) {
            as0 += __shfl_down_sync(0xFFFFFFFFu, as0, o, 16);
            ad0 += __shfl_down_sync(0xFFFFFFFFu, ad0, o, 16);
            as1 += __shfl_down_sync(0xFFFFFFFFu, as1, o, 16);
            ad1 += __shfl_down_sync(0xFFFFFFFFu, ad1, o, 16);
        }
        if ((lane & 15) == 0) {
            if (row0 < N_NODES) { g_asrc[row0 * 4 + head] = as0; g_adst[row0 * 4 + head] = ad0; }
            if (row1 < N_NODES) { g_asrc[row1 * 4 + head] = as1; g_adst[row1 * 4 + head] = ad1; }
        }
    }
}

// ---------------------------------------------------------------------------
__global__ void hist_kernel(const void* __restrict__ ei) {
    int i = blockIdx.x * blockDim.x + threadIdx.x;
    if (i < NE) {
        int d = load_edge(ei, NE + i);
        if ((unsigned)d < (unsigned)N_NODES) atomicAdd(&g_cnt[d], 1);
    }
}

__global__ __launch_bounds__(1024) void scan1_kernel() {
    __shared__ int sh[1024];
    int i = blockIdx.x * 1024 + threadIdx.x;
    int v = (i < N_NODES) ? g_cnt[i] : 0;
    sh[threadIdx.x] = v; __syncthreads();
    for (int off = 1; off < 1024; off <<= 1) {
        int t = (threadIdx.x >= off) ? sh[threadIdx.x - off] : 0;
        __syncthreads();
        sh[threadIdx.x] += t; __syncthreads();
    }
    if (i < N_NODES) g_rowptr[i] = sh[threadIdx.x] - v;  // exclusive
    if (threadIdx.x == 1023) g_part[blockIdx.x] = sh[1023];
}

__global__ __launch_bounds__(128) void scan2_kernel(int nb) {
    __shared__ int sh[128];
    int v = (threadIdx.x < nb) ? g_part[threadIdx.x] : 0;
    sh[threadIdx.x] = v; __syncthreads();
    for (int off = 1; off < 128; off <<= 1) {
        int t = (threadIdx.x >= off) ? sh[threadIdx.x - off] : 0;
        __syncthreads();
        sh[threadIdx.x] += t; __syncthreads();
    }
    if (threadIdx.x < nb) g_part2[threadIdx.x] = sh[threadIdx.x] - v;
    if (threadIdx.x == nb - 1) g_rowptr[N_NODES] = sh[threadIdx.x]; // total valid
}

__global__ __launch_bounds__(1024) void scan3_kernel() {
    int i = blockIdx.x * 1024 + threadIdx.x;
    if (i < N_NODES) {
        int v = g_rowptr[i] + g_part2[blockIdx.x];
        g_rowptr[i] = v;
        g_fill[i] = v;
    }
}

__global__ void fill_kernel(const void* __restrict__ ei) {
    int i = blockIdx.x * blockDim.x + threadIdx.x;
    if (i < NE) {
        int s = load_edge(ei, i);
        int d = load_edge(ei, NE + i);
        if ((unsigned)s < (unsigned)N_NODES && (unsigned)d < (unsigned)N_NODES) {
            int pos = atomicAdd(&g_fill[d], 1);
            g_csr[pos] = s;
        }
    }
}

// ---------------------------------------------------------------------------
// Aggregate: one WARP per (node, head), single pass, fp16 gathers (one 128B
// line per edge per warp); lane owns channel pair (2*lane, 2*lane+1).
__global__ __launch_bounds__(256) void agg_kernel(const float* __restrict__ bias,
                                                  float* __restrict__ out) {
    const int warp = threadIdx.x >> 5;
    const int lane = threadIdx.x & 31;
    const int node = blockIdx.x * 2 + (warp >> 2);
    const int hd   = warp & 3;
    if (node >= N_NODES) return;

    const int ebase = g_rowptr[node];
    const int deg   = g_rowptr[node + 1] - ebase;
    const float adh = g_adst[node * 4 + hd];
    const int   off = hd * 64;

    // self-loop (unnormalized)
    float e = g_asrc[node * 4 + hd] + adh;
    e = e > 0.f ? e : NEG * e;
    const float exself = __expf(e);

    const float2 hv = __half22float2(((const __half2*)(g_h16 + (size_t)node * 256 + off))[lane]);
    float ax0 = hv.x * exself, ay0 = hv.y * exself;
    float ax1 = 0.f, ay1 = 0.f;
    float den = 0.f;   // lane-local partial of edge exp-sum

    for (int base = 0; base < deg; base += 32) {
        const int m = min(32, deg - base);
        int   sl = 0; float al = 0.f;
        if (lane < m) {
            sl = g_csr[ebase + base + lane];
            float t = g_asrc[sl * 4 + hd] + adh;
            t = t > 0.f ? t : NEG * t;
            al = __expf(t);
        }
        den += al;
        int k = 0;
        for (; k + 4 <= m; k += 4) {
            int   s0 = __shfl_sync(0xFFFFFFFFu, sl, k);
            int   s1 = __shfl_sync(0xFFFFFFFFu, sl, k + 1);
            int   s2 = __shfl_sync(0xFFFFFFFFu, sl, k + 2);
            int   s3 = __shfl_sync(0xFFFFFFFFu, sl, k + 3);
            float w0 = __shfl_sync(0xFFFFFFFFu, al, k);
            float w1 = __shfl_sync(0xFFFFFFFFu, al, k + 1);
            float w2 = __shfl_sync(0xFFFFFFFFu, al, k + 2);
            float w3 = __shfl_sync(0xFFFFFFFFu, al, k + 3);
            __half2 v0 = ((const __half2*)(g_h16 + (size_t)s0 * 256 + off))[lane];
            __half2 v1 = ((const __half2*)(g_h16 + (size_t)s1 * 256 + off))[lane];
            __half2 v2 = ((const __half2*)(g_h16 + (size_t)s2 * 256 + off))[lane];
            __half2 v3 = ((const __half2*)(g_h16 + (size_t)s3 * 256 + off))[lane];
            float2 f0 = __half22float2(v0);
            float2 f1 = __half22float2(v1);
            float2 f2 = __half22float2(v2);
            float2 f3 = __half22float2(v3);
            ax0 += f0.x * w0;  ay0 += f0.y * w0;
            ax1 += f1.x * w1;  ay1 += f1.y * w1;
            ax0 += f2.x * w2;  ay0 += f2.y * w2;
            ax1 += f3.x * w3;  ay1 += f3.y * w3;
        }
        for (; k < m; k++) {
            int   s0 = __shfl_sync(0xFFFFFFFFu, sl, k);
            float w0 = __shfl_sync(0xFFFFFFFFu, al, k);
            __half2 v0 = ((const __half2*)(g_h16 + (size_t)s0 * 256 + off))[lane];
            float2 f0 = __half22float2(v0);
            ax0 += f0.x * w0;  ay0 += f0.y * w0;
        }
    }
    #pragma unroll
    for (int o = 16; o; o >>= 1) den += __shfl_xor_sync(0xFFFFFFFFu, den, o);
    const float inv = 1.f / (den + exself + 1e-16f);

    const float2 bv = ((const float2*)(bias + off))[lane];
    float2 res;
    res.x = (ax0 + ax1) * inv + bv.x;
    res.y = (ay0 + ay1) * inv + bv.y;
    ((float2*)(out + (size_t)node * 256 + off))[lane] = res;
}

// ---------------------------------------------------------------------------
__global__ __launch_bounds__(256) void bnstat_kernel(const float* __restrict__ out) {
    int t = threadIdx.x;
    int r0 = blockIdx.x * 256;
    int rmax = min(256, N_NODES - r0);
    float s = 0.f, s2 = 0.f;
    for (int r = 0; r < rmax; r++) {
        float v = out[(size_t)(r0 + r) * 256 + t];
        s += v; s2 += v * v;
    }
    atomicAdd(&g_stat[t], s);
    atomicAdd(&g_stat[256 + t], s2);
}

__global__ __launch_bounds__(256) void bnfin_kernel(const float* __restrict__ gamma,
                                                    const float* __restrict__ beta) {
    int t = threadIdx.x;
    float invN = 1.f / (float)N_NODES;
    float mean = g_stat[t] * invN;
    float var = g_stat[256 + t] * invN - mean * mean;
    float sc = gamma[t] * rsqrtf(var + BNEPS);
    g_scale[t] = sc;
    g_shift[t] = beta[t] - mean * sc;
}

__global__ __launch_bounds__(256) void final_kernel(float* __restrict__ out) {
    int i4 = blockIdx.x * 256 + threadIdx.x;
    if (i4 >= N_NODES * (HC / 4)) return;
    int c = (i4 & 63) * 4;
    float4 v = ((float4*)out)[i4];
    float f;
    f = g_scale[c + 0] * v.x + g_shift[c + 0]; v.x = f > 0.f ? f : expm1f(f);
    f = g_scale[c + 1] * v.y + g_shift[c + 1]; v.y = f > 0.f ? f : expm1f(f);
    f = g_scale[c + 2] * v.z + g_shift[c + 2]; v.z = f > 0.f ? f : expm1f(f);
    f = g_scale[c + 3] * v.w + g_shift[c + 3]; v.w = f > 0.f ? f : expm1f(f);
    ((float4*)out)[i4] = v;
}

// ---------------------------------------------------------------------------
extern "C" void kernel_launch(void* const* d_in, const int* in_sizes, int n_in,
                              void* d_out, int out_size) {
    const float* x       = (const float*)d_in[0];
    const void*  ei      = d_in[1];
    const float* W       = (const float*)d_in[2];
    const float* att_src = (const float*)d_in[3];
    const float* att_dst = (const float*)d_in[4];
    const float* bias    = (const float*)d_in[5];
    const float* gamma   = (const float*)d_in[6];
    const float* beta    = (const float*)d_in[7];
    float* out = (float*)d_out;

    // lazy one-time side stream + fork/join events (host objects, no device
    // memory allocation; identical launch sequence every call)
    static cudaStream_t s_side = 0;
    static cudaEvent_t  ev_fork = 0, ev_join = 0;
    if (!s_side) {
        cudaStreamCreateWithFlags(&s_side, cudaStreamNonBlocking);
        cudaEventCreateWithFlags(&ev_fork, cudaEventDisableTiming);
        cudaEventCreateWithFlags(&ev_join, cudaEventDisableTiming);
    }

    // fork: CSR build chain on side stream, concurrent with GEMM
    cudaEventRecord(ev_fork, 0);
    cudaStreamWaitEvent(s_side, ev_fork, 0);

    probe_kernel<<<1, 1, 0, s_side>>>((const int*)ei);
    init_kernel<<<(N_NODES + 255) / 256, 256, 0, s_side>>>();
    hist_kernel<<<(NE + 255) / 256, 256, 0, s_side>>>(ei);
    int nb = (N_NODES + 1023) / 1024;   // 98
    scan1_kernel<<<nb, 1024, 0, s_side>>>();
    scan2_kernel<<<1, 128, 0, s_side>>>(nb);
    scan3_kernel<<<nb, 1024, 0, s_side>>>();
    fill_kernel<<<(NE + 255) / 256, 256, 0, s_side>>>(ei);
    cudaEventRecord(ev_join, s_side);

    gemm_kernel<<<(N_NODES + 63) / 64, 256>>>(x, W, att_src, att_dst);

    // join: agg needs both GEMM (default stream) and CSR (side stream)
    cudaStreamWaitEvent(0, ev_join, 0);

    agg_kernel<<<(N_NODES + 1) / 2, 256>>>(bias, out);

    bnstat_kernel<<<(N_NODES + 255) / 256, 256>>>(out);
    bnfin_kernel<<<1, 256>>>(gamma, beta);
    final_kernel<<<(N_NODES * (HC / 4) + 255) / 256, 256>>>(out);
}